// round 12
// baseline (speedup 1.0000x reference)
#include <cuda_runtime.h>
#include <cuda_bf16.h>

#define NNODES 50000
#define NEDGES 800000
#define NB 4
#define NIN 32
#define H2 30

typedef unsigned long long ull;

#define CONV_BLOCKS (NEDGES / 256)                       // 3125
#define PRE_BLOCKS  ((NB * NNODES * 32) / 256)           // 25000

// ---------------- device scratch ----------------
__device__ double g_stats[2];
__device__ float  g_norm[2];
__device__ int    g_is64;
__device__ int    g_src[NEDGES];
__device__ int    g_tgt[NEDGES];
__device__ __align__(16) __nv_bfloat16 g_Pb[NB * NNODES * 32];
__device__ __align__(16) __nv_bfloat16 g_Qb[NB * NNODES * 32];
__device__ __align__(16) float g_acc[NB * NNODES * 32];

__device__ __forceinline__ float sigm(float x) {
    return __fdividef(1.0f, 1.0f + __expf(-x));
}
__device__ __forceinline__ float sigm_fast(float x) {
    float t;
    asm("tanh.approx.f32 %0, %1;" : "=f"(t) : "f"(x * 0.5f));
    return fmaf(0.5f, t, 0.5f);
}
__device__ __forceinline__ ull pack2(float lo, float hi) {
    ull r;
    asm("mov.b64 %0, {%1,%2};" : "=l"(r) : "r"(__float_as_uint(lo)), "r"(__float_as_uint(hi)));
    return r;
}
__device__ __forceinline__ ull bcast2(float v) {
    ull r;
    asm("mov.b64 %0, {%1,%1};" : "=l"(r) : "r"(__float_as_uint(v)));
    return r;
}

// ---------------- 1. detect dtype + zero stats ----------------
__global__ void k_detect(const int* __restrict__ ei) {
    int odd_or = 0;
    for (int k = 1; k < 128; k += 2) odd_or |= ei[k];
    g_is64 = (odd_or == 0) ? 1 : 0;
    g_stats[0] = 0.0;
    g_stats[1] = 0.0;
}

// ---------------- 2. megakernel: convert+stats | precompute+zero ----------------
__global__ void k_prep(const int* __restrict__ ei, const float* __restrict__ ea,
                       const float* __restrict__ x, const float* __restrict__ W1,
                       const float* __restrict__ b1) {
    if (blockIdx.x < CONV_BLOCKS) {
        __shared__ float s1[8], s2[8];
        int e = blockIdx.x * 256 + threadIdx.x;          // grid covers exactly NEDGES
        int s, t;
        if (g_is64) {
            const long long* e64 = (const long long*)ei;
            s = (int)e64[e];
            t = (int)e64[NEDGES + e];
        } else {
            s = ei[e];
            t = ei[NEDGES + e];
        }
        s = min(max(s, 0), NNODES - 1);
        t = min(max(t, 0), NNODES - 1);
        g_src[e] = s;
        g_tgt[e] = t;

        float v = ea[e];
        float v1 = v, v2 = v * v;
        #pragma unroll
        for (int o = 16; o > 0; o >>= 1) {
            v1 += __shfl_xor_sync(0xffffffffu, v1, o);
            v2 += __shfl_xor_sync(0xffffffffu, v2, o);
        }
        int w = threadIdx.x >> 5;
        if ((threadIdx.x & 31) == 0) { s1[w] = v1; s2[w] = v2; }
        __syncthreads();
        if (threadIdx.x == 0) {
            float t1 = 0.0f, t2 = 0.0f;
            #pragma unroll
            for (int i = 0; i < 8; i++) { t1 += s1[i]; t2 += s2[i]; }
            atomicAdd(&g_stats[0], (double)t1);
            atomicAdd(&g_stats[1], (double)t2);
        }
    } else {
        int tid = (blockIdx.x - CONV_BLOCKS) * 256 + threadIdx.x;
        int j   = tid & 31;
        int row = tid >> 5;
        const float* xr = x + (size_t)row * NIN;
        float p = 0.0f;
        float q = b1[j];
        #pragma unroll
        for (int i = 0; i < NIN; i++) {
            float xi = __ldg(&xr[i]);
            p = fmaf(xi, __ldg(&W1[i * 32 + j]), p);
            q = fmaf(xi, __ldg(&W1[(32 + i) * 32 + j]), q);
        }
        g_Pb[tid] = __float2bfloat16(p);
        g_Qb[tid] = __float2bfloat16(q);
        g_acc[tid] = 0.0f;
    }
}

// ---------------- 3. finalize stats ----------------
__global__ void k_finalize_stats() {
    double s = g_stats[0], ss = g_stats[1];
    double n = (double)NEDGES;
    double mean = s / n;
    double var = (ss - s * s / n) / (n - 1.0);   // ddof=1
    g_norm[0] = (float)mean;
    g_norm[1] = (float)(1.0 / sqrt(var));
}

// ---------------- 4. edge kernel (PROFILED SLOT) — quad-cooperative ----------------
// 4 lanes = 1 edge; lane owns channel chunk [8c, 8c+8).
__global__ __launch_bounds__(256) void k_edge(const float* __restrict__ ea,
                                              const float* __restrict__ W1,
                                              const float* __restrict__ W2,
                                              const float* __restrict__ b2) {
    __shared__ __align__(16) ull sW2p[32 * 16];   // [j][m]: (W2[j][2m], W2[j][2m+1]), padded
    __shared__ float sw1c[32];
    __shared__ ull   sb2p[16];

    for (int idx = threadIdx.x; idx < 512; idx += 256) {
        int j = idx >> 4, m = idx & 15;
        float w0 = (2 * m     < H2) ? W2[j * H2 + 2 * m]     : 0.0f;
        float w1 = (2 * m + 1 < H2) ? W2[j * H2 + 2 * m + 1] : 0.0f;
        sW2p[idx] = pack2(w0, w1);
    }
    if (threadIdx.x < 32) {
        sw1c[threadIdx.x] = W1[64 * 32 + threadIdx.x];
    }
    if (threadIdx.x < 16) {
        int m = threadIdx.x;
        float d0 = (2 * m     < H2) ? b2[2 * m]     : 0.0f;
        float d1 = (2 * m + 1 < H2) ? b2[2 * m + 1] : 0.0f;
        sb2p[m] = pack2(d0, d1);
    }
    __syncthreads();

    int lane = threadIdx.x & 31;
    int warp = threadIdx.x >> 5;
    int c    = lane & 3;                          // chunk 0..3 (channels 8c..8c+7)
    int eq   = lane >> 2;                         // edge-in-warp 0..7

    int e = blockIdx.x * 64 + warp * 8 + eq;      // NEDGES % 64 == 0
    int b = blockIdx.y;
    size_t bbase = (size_t)b * NNODES;

    int src = g_src[e];                           // quad-uniform (broadcast)
    int tgt = g_tgt[e];
    float ean = (ea[e] - g_norm[0]) * g_norm[1];

    // gather this lane's 16B chunk of P/Q rows
    uint4 pv = ((const uint4*)(g_Pb + (bbase + src) * 32))[c];
    uint4 qv = ((const uint4*)(g_Qb + (bbase + tgt) * 32))[c];

    const __nv_bfloat162* pb = (const __nv_bfloat162*)&pv;
    const __nv_bfloat162* qb = (const __nv_bfloat162*)&qv;

    // layer-1 + sigmoid for this lane's 8 j-channels, packed as 4 f32x2
    ull aPack[4];
    #pragma unroll
    for (int i = 0; i < 4; i++) {
        float2 pf = __bfloat1622float2(pb[i]);
        float2 qf = __bfloat1622float2(qb[i]);
        int ch = 8 * c + 2 * i;
        float a0 = sigm_fast(pf.x + qf.x + ean * sw1c[ch + 0]);
        float a1 = sigm_fast(pf.y + qf.y + ean * sw1c[ch + 1]);
        aPack[i] = pack2(a0, a1);
    }

    // quad exchange: collect all 32 a's as 16 pairs (a_2m, a_2m+1)
    ull aAll[16];
    #pragma unroll
    for (int i = 0; i < 4; i++) aAll[c * 4 + i] = aPack[i];
    #pragma unroll
    for (int p = 1; p < 4; p++) {
        int cp = c ^ p;
        #pragma unroll
        for (int i = 0; i < 4; i++) {
            aAll[cp * 4 + i] = __shfl_xor_sync(0xffffffffu, aPack[i], p);
        }
    }

    // layer-2: this lane accumulates channels [8c, 8c+8) over all 32 j
    ull h[4];
    #pragma unroll
    for (int i = 0; i < 4; i++) h[i] = sb2p[4 * c + i];

    #pragma unroll
    for (int m = 0; m < 16; m++) {                // j = 2m, 2m+1
        unsigned lo, hi;
        asm("mov.b64 {%0,%1}, %2;" : "=r"(lo), "=r"(hi) : "l"(aAll[m]));
        ull ap0, ap1;
        asm("mov.b64 %0, {%1,%1};" : "=l"(ap0) : "r"(lo));
        asm("mov.b64 %0, {%1,%1};" : "=l"(ap1) : "r"(hi));

        const ulonglong2* w0 = (const ulonglong2*)&sW2p[(2 * m) * 16 + 4 * c];
        const ulonglong2* w1 = (const ulonglong2*)&sW2p[(2 * m + 1) * 16 + 4 * c];
        ulonglong2 wa = w0[0];
        ulonglong2 wb = w0[1];
        ulonglong2 wc = w1[0];
        ulonglong2 wd = w1[1];
        asm("fma.rn.f32x2 %0, %1, %2, %0;" : "+l"(h[0]) : "l"(ap0), "l"(wa.x));
        asm("fma.rn.f32x2 %0, %1, %2, %0;" : "+l"(h[1]) : "l"(ap0), "l"(wa.y));
        asm("fma.rn.f32x2 %0, %1, %2, %0;" : "+l"(h[2]) : "l"(ap0), "l"(wb.x));
        asm("fma.rn.f32x2 %0, %1, %2, %0;" : "+l"(h[3]) : "l"(ap0), "l"(wb.y));
        asm("fma.rn.f32x2 %0, %1, %2, %0;" : "+l"(h[0]) : "l"(ap1), "l"(wc.x));
        asm("fma.rn.f32x2 %0, %1, %2, %0;" : "+l"(h[1]) : "l"(ap1), "l"(wc.y));
        asm("fma.rn.f32x2 %0, %1, %2, %0;" : "+l"(h[2]) : "l"(ap1), "l"(wd.x));
        asm("fma.rn.f32x2 %0, %1, %2, %0;" : "+l"(h[3]) : "l"(ap1), "l"(wd.y));
    }

    // sigmoid on this lane's 8 output channels (zero the pad channels 30,31)
    float h2[8];
    #pragma unroll
    for (int i = 0; i < 4; i++) {
        unsigned lo, hi;
        asm("mov.b64 {%0,%1}, %2;" : "=r"(lo), "=r"(hi) : "l"(h[i]));
        h2[2 * i + 0] = sigm_fast(__uint_as_float(lo));
        h2[2 * i + 1] = sigm_fast(__uint_as_float(hi));
    }
    if (c == 3) { h2[6] = 0.0f; h2[7] = 0.0f; }   // channels 30,31

    float4 hv0 = make_float4(h2[0], h2[1], h2[2], h2[3]);
    float4 hv1 = make_float4(h2[4], h2[5], h2[6], h2[7]);

    float* at = &g_acc[(bbase + tgt) * 32 + 8 * c];
    float* as = &g_acc[(bbase + src) * 32 + 8 * c];
    atomicAdd((float4*)at,       hv0);
    atomicAdd((float4*)(at + 4), hv1);
    atomicAdd((float4*)as,       make_float4(-hv0.x, -hv0.y, -hv0.z, -hv0.w));
    atomicAdd((float4*)(as + 4), make_float4(-hv1.x, -hv1.y, -hv1.z, -hv1.w));
}

// ---------------- 5. epilogue ----------------
__global__ void k_out(const float* __restrict__ W3,
                      const float* __restrict__ b3,
                      float* __restrict__ out) {
    int tid = blockIdx.x * 256 + threadIdx.x;
    if (tid >= NB * NNODES * 32) return;
    int j   = tid & 31;
    int row = tid >> 5;
    const float* ar = &g_acc[(size_t)row * 32];
    float o = b3[j];
    #pragma unroll
    for (int k = 0; k < H2; k++) {
        o = fmaf(ar[k], __ldg(&W3[k * 32 + j]), o);
    }
    out[tid] = sigm(o);
}

// ---------------- launch ----------------
extern "C" void kernel_launch(void* const* d_in, const int* in_sizes, int n_in,
                              void* d_out, int out_size) {
    const void* p_x = 0;  const void* p_ei = 0; const void* p_ea = 0;
    const void* p_W1 = 0; const void* p_b1 = 0; const void* p_W2 = 0;
    const void* p_b2 = 0; const void* p_W3 = 0; const void* p_b3 = 0;
    for (int i = 0; i < n_in; i++) {
        int s = in_sizes[i];
        const void* p = d_in[i];
        if      (s == NB * NNODES * NIN)  p_x = p;
        else if (s == 2 * NEDGES)         p_ei = p;
        else if (s == NEDGES)             p_ea = p;
        else if (s == (2 * NIN + 1) * 32) p_W1 = p;
        else if (s == 32 * H2)            { if (!p_W2) p_W2 = p; else p_W3 = p; }
        else if (s == 32)                 { if (!p_b1) p_b1 = p; else p_b3 = p; }
        else if (s == H2)                 p_b2 = p;
    }
    const float* x  = (const float*)p_x;
    const int*   ei = (const int*)p_ei;
    const float* ea = (const float*)p_ea;
    const float* W1 = (const float*)p_W1;
    const float* b1 = (const float*)p_b1;
    const float* W2 = (const float*)p_W2;
    const float* b2 = (const float*)p_b2;
    const float* W3 = (const float*)p_W3;
    const float* b3 = (const float*)p_b3;
    float* out = (float*)d_out;

    k_detect<<<1, 1>>>(ei);                                          // 1
    k_prep<<<CONV_BLOCKS + PRE_BLOCKS, 256>>>(ei, ea, x, W1, b1);    // 2
    k_finalize_stats<<<1, 1>>>();                                    // 3
    dim3 egrid(NEDGES / 64, NB);
    k_edge<<<egrid, 256>>>(ea, W1, W2, b2);                          // 4  <- profiled slot
    k_out<<<(NB * NNODES * 32 + 255) / 256, 256>>>(W3, b3, out);     // 5
}

// round 13
// speedup vs baseline: 2.2591x; 2.2591x over previous
#include <cuda_runtime.h>
#include <cuda_bf16.h>

#define NNODES 50000
#define NEDGES 800000
#define NB 4
#define NIN 32
#define H2 30

typedef unsigned long long ull;

#define CONV_BLOCKS (NEDGES / 256)                       // 3125
#define PRE_BLOCKS  ((NB * NNODES * 32) / 256)           // 25000
#define ROWB 80                                          // staging row stride (bytes)
#define HROWB 144                                        // h-bounce row stride (bytes)

// ---------------- device scratch ----------------
__device__ double g_stats[2];
__device__ float  g_norm[2];
__device__ int    g_is64;
__device__ int    g_src[NEDGES];
__device__ int    g_tgt[NEDGES];
__device__ __align__(16) __nv_bfloat16 g_Pb[NB * NNODES * 32];
__device__ __align__(16) __nv_bfloat16 g_Qb[NB * NNODES * 32];
__device__ __align__(16) float g_acc[NB * NNODES * 32];

__device__ __forceinline__ float sigm(float x) {
    return __fdividef(1.0f, 1.0f + __expf(-x));
}
__device__ __forceinline__ float sigm_fast(float x) {
    float t;
    asm("tanh.approx.f32 %0, %1;" : "=f"(t) : "f"(x * 0.5f));
    return fmaf(0.5f, t, 0.5f);
}
__device__ __forceinline__ ull pack2(float lo, float hi) {
    ull r;
    asm("mov.b64 %0, {%1,%2};" : "=l"(r) : "r"(__float_as_uint(lo)), "r"(__float_as_uint(hi)));
    return r;
}
__device__ __forceinline__ ull bcast2(float v) {
    ull r;
    asm("mov.b64 %0, {%1,%1};" : "=l"(r) : "r"(__float_as_uint(v)));
    return r;
}

// ---------------- 1. detect dtype + zero stats ----------------
__global__ void k_detect(const int* __restrict__ ei) {
    int odd_or = 0;
    for (int k = 1; k < 128; k += 2) odd_or |= ei[k];
    g_is64 = (odd_or == 0) ? 1 : 0;
    g_stats[0] = 0.0;
    g_stats[1] = 0.0;
}

// ---------------- 2. megakernel: convert+stats | precompute+zero ----------------
__global__ void k_prep(const int* __restrict__ ei, const float* __restrict__ ea,
                       const float* __restrict__ x, const float* __restrict__ W1,
                       const float* __restrict__ b1) {
    if (blockIdx.x < CONV_BLOCKS) {
        __shared__ float s1[8], s2[8];
        int e = blockIdx.x * 256 + threadIdx.x;          // grid covers exactly NEDGES
        int s, t;
        if (g_is64) {
            const long long* e64 = (const long long*)ei;
            s = (int)e64[e];
            t = (int)e64[NEDGES + e];
        } else {
            s = ei[e];
            t = ei[NEDGES + e];
        }
        s = min(max(s, 0), NNODES - 1);
        t = min(max(t, 0), NNODES - 1);
        g_src[e] = s;
        g_tgt[e] = t;

        float v = ea[e];
        float v1 = v, v2 = v * v;
        #pragma unroll
        for (int o = 16; o > 0; o >>= 1) {
            v1 += __shfl_xor_sync(0xffffffffu, v1, o);
            v2 += __shfl_xor_sync(0xffffffffu, v2, o);
        }
        int w = threadIdx.x >> 5;
        if ((threadIdx.x & 31) == 0) { s1[w] = v1; s2[w] = v2; }
        __syncthreads();
        if (threadIdx.x == 0) {
            float t1 = 0.0f, t2 = 0.0f;
            #pragma unroll
            for (int i = 0; i < 8; i++) { t1 += s1[i]; t2 += s2[i]; }
            atomicAdd(&g_stats[0], (double)t1);
            atomicAdd(&g_stats[1], (double)t2);
        }
    } else {
        int tid = (blockIdx.x - CONV_BLOCKS) * 256 + threadIdx.x;
        int j   = tid & 31;
        int row = tid >> 5;
        const float* xr = x + (size_t)row * NIN;
        float p = 0.0f;
        float q = b1[j];
        #pragma unroll
        for (int i = 0; i < NIN; i++) {
            float xi = __ldg(&xr[i]);
            p = fmaf(xi, __ldg(&W1[i * 32 + j]), p);
            q = fmaf(xi, __ldg(&W1[(32 + i) * 32 + j]), q);
        }
        g_Pb[tid] = __float2bfloat16(p);
        g_Qb[tid] = __float2bfloat16(q);
        g_acc[tid] = 0.0f;
    }
}

// ---------------- 3. finalize stats ----------------
__global__ void k_finalize_stats() {
    double s = g_stats[0], ss = g_stats[1];
    double n = (double)NEDGES;
    double mean = s / n;
    double var = (ss - s * s / n) / (n - 1.0);   // ddof=1
    g_norm[0] = (float)mean;
    g_norm[1] = (float)(1.0 / sqrt(var));
}

// ---------------- 4. edge kernel (PROFILED SLOT) ----------------
// Compute: 1 edge/thread (R11). Scatter: octet-cooperative via smem bounce.
__global__ __launch_bounds__(256) void k_edge(const float* __restrict__ ea,
                                              const float* __restrict__ W1,
                                              const float* __restrict__ W2,
                                              const float* __restrict__ b2) {
    __shared__ __align__(16) ull  sW2p[32 * 16];
    __shared__ float sw1c[32];
    __shared__ ull   sb2p[16];
    __shared__ __align__(16) char sBuf[256 * 2 * ROWB];  // stage P/Q; then h-bounce (256*144 fits)
    __shared__ int  sIdx[256 * 2];                       // [row]: src, tgt

    char* sP = sBuf;
    char* sQ = sBuf + 256 * ROWB;

    for (int idx = threadIdx.x; idx < 512; idx += 256) {
        int j = idx >> 4, m = idx & 15;
        float w0 = (2 * m     < H2) ? W2[j * H2 + 2 * m]     : 0.0f;
        float w1 = (2 * m + 1 < H2) ? W2[j * H2 + 2 * m + 1] : 0.0f;
        sW2p[idx] = pack2(w0, w1);
    }
    if (threadIdx.x < 32) {
        sw1c[threadIdx.x] = W1[64 * 32 + threadIdx.x];
    }
    if (threadIdx.x < 16) {
        int m = threadIdx.x;
        float d0 = (2 * m     < H2) ? b2[2 * m]     : 0.0f;
        float d1 = (2 * m + 1 < H2) ? b2[2 * m + 1] : 0.0f;
        sb2p[m] = pack2(d0, d1);
    }

    int b = blockIdx.y;
    size_t bbase = (size_t)b * NNODES;
    int e0 = blockIdx.x * 256;                    // NEDGES % 256 == 0

    // ---- cooperative gather: quad (4 lanes) loads one 64B row ----
    {
        int chunk = threadIdx.x & 3;
        int row4  = threadIdx.x >> 2;             // 0..63
        #pragma unroll
        for (int it = 0; it < 4; it++) {
            int row = row4 + it * 64;
            int e = e0 + row;
            int src = g_src[e];
            int tgt = g_tgt[e];
            const uint4* Pr = (const uint4*)(g_Pb + (bbase + src) * 32);
            const uint4* Qr = (const uint4*)(g_Qb + (bbase + tgt) * 32);
            *(uint4*)(sP + row * ROWB + chunk * 16) = Pr[chunk];
            *(uint4*)(sQ + row * ROWB + chunk * 16) = Qr[chunk];
            if (chunk == 0) {
                sIdx[row * 2 + 0] = src;
                sIdx[row * 2 + 1] = tgt;
            }
        }
    }
    __syncthreads();

    int e = e0 + threadIdx.x;
    float ean = (ea[e] - g_norm[0]) * g_norm[1];

    const uint4* myP = (const uint4*)(sP + threadIdx.x * ROWB);
    const uint4* myQ = (const uint4*)(sQ + threadIdx.x * ROWB);
    uint4 pv[4], qv[4];
    #pragma unroll
    for (int m = 0; m < 4; m++) { pv[m] = myP[m]; qv[m] = myQ[m]; }

    const __nv_bfloat162* pb = (const __nv_bfloat162*)pv;
    const __nv_bfloat162* qb = (const __nv_bfloat162*)qv;

    float z1[32];
    #pragma unroll
    for (int m = 0; m < 16; m++) {
        float2 pf = __bfloat1622float2(pb[m]);
        float2 qf = __bfloat1622float2(qb[m]);
        z1[2 * m + 0] = pf.x + qf.x + ean * sw1c[2 * m + 0];
        z1[2 * m + 1] = pf.y + qf.y + ean * sw1c[2 * m + 1];
    }

    ull h2p[16];
    #pragma unroll
    for (int m = 0; m < 16; m++) h2p[m] = sb2p[m];

    #pragma unroll
    for (int j = 0; j < 32; j++) {
        ull ap = bcast2(sigm_fast(z1[j]));
        const ulonglong2* wr = (const ulonglong2*)&sW2p[j * 16];
        #pragma unroll
        for (int m = 0; m < 8; m++) {
            ulonglong2 w = wr[m];
            asm("fma.rn.f32x2 %0, %1, %2, %0;" : "+l"(h2p[2 * m + 0]) : "l"(ap), "l"(w.x));
            asm("fma.rn.f32x2 %0, %1, %2, %0;" : "+l"(h2p[2 * m + 1]) : "l"(ap), "l"(w.y));
        }
    }

    float h2[32];
    #pragma unroll
    for (int m = 0; m < 16; m++) {
        unsigned lo, hi;
        asm("mov.b64 {%0,%1}, %2;" : "=r"(lo), "=r"(hi) : "l"(h2p[m]));
        h2[2 * m + 0] = sigm_fast(__uint_as_float(lo));
        h2[2 * m + 1] = sigm_fast(__uint_as_float(hi));
    }
    h2[30] = 0.0f;   // pad channels must not scatter sigmoid(0)
    h2[31] = 0.0f;

    // ---- bounce h2 through smem (overwrites staging buffer) ----
    __syncthreads();                              // all P/Q reads done
    {
        float4* myH = (float4*)(sBuf + threadIdx.x * HROWB);
        #pragma unroll
        for (int m = 0; m < 8; m++)
            myH[m] = make_float4(h2[4 * m + 0], h2[4 * m + 1], h2[4 * m + 2], h2[4 * m + 3]);
    }
    __syncthreads();

    // ---- octet-cooperative scatter: 8 lanes = 1 edge, lane owns chunk oc ----
    {
        int oc  = threadIdx.x & 7;                // 16B chunk 0..7
        int oct = threadIdx.x >> 3;               // 0..31
        #pragma unroll
        for (int it = 0; it < 8; it++) {
            int row = oct + it * 32;              // 0..255
            int src = sIdx[row * 2 + 0];
            int tgt = sIdx[row * 2 + 1];
            float4 hv = *(const float4*)(sBuf + row * HROWB + oc * 16);
            atomicAdd((float4*)&g_acc[(bbase + tgt) * 32 + oc * 4], hv);
            atomicAdd((float4*)&g_acc[(bbase + src) * 32 + oc * 4],
                      make_float4(-hv.x, -hv.y, -hv.z, -hv.w));
        }
    }
}

// ---------------- 5. epilogue ----------------
__global__ void k_out(const float* __restrict__ W3,
                      const float* __restrict__ b3,
                      float* __restrict__ out) {
    int tid = blockIdx.x * 256 + threadIdx.x;
    if (tid >= NB * NNODES * 32) return;
    int j   = tid & 31;
    int row = tid >> 5;
    const float* ar = &g_acc[(size_t)row * 32];
    float o = b3[j];
    #pragma unroll
    for (int k = 0; k < H2; k++) {
        o = fmaf(ar[k], __ldg(&W3[k * 32 + j]), o);
    }
    out[tid] = sigm(o);
}

// ---------------- launch ----------------
extern "C" void kernel_launch(void* const* d_in, const int* in_sizes, int n_in,
                              void* d_out, int out_size) {
    const void* p_x = 0;  const void* p_ei = 0; const void* p_ea = 0;
    const void* p_W1 = 0; const void* p_b1 = 0; const void* p_W2 = 0;
    const void* p_b2 = 0; const void* p_W3 = 0; const void* p_b3 = 0;
    for (int i = 0; i < n_in; i++) {
        int s = in_sizes[i];
        const void* p = d_in[i];
        if      (s == NB * NNODES * NIN)  p_x = p;
        else if (s == 2 * NEDGES)         p_ei = p;
        else if (s == NEDGES)             p_ea = p;
        else if (s == (2 * NIN + 1) * 32) p_W1 = p;
        else if (s == 32 * H2)            { if (!p_W2) p_W2 = p; else p_W3 = p; }
        else if (s == 32)                 { if (!p_b1) p_b1 = p; else p_b3 = p; }
        else if (s == H2)                 p_b2 = p;
    }
    const float* x  = (const float*)p_x;
    const int*   ei = (const int*)p_ei;
    const float* ea = (const float*)p_ea;
    const float* W1 = (const float*)p_W1;
    const float* b1 = (const float*)p_b1;
    const float* W2 = (const float*)p_W2;
    const float* b2 = (const float*)p_b2;
    const float* W3 = (const float*)p_W3;
    const float* b3 = (const float*)p_b3;
    float* out = (float*)d_out;

    k_detect<<<1, 1>>>(ei);                                          // 1
    k_prep<<<CONV_BLOCKS + PRE_BLOCKS, 256>>>(ei, ea, x, W1, b1);    // 2
    k_finalize_stats<<<1, 1>>>();                                    // 3
    dim3 egrid(CONV_BLOCKS, NB);
    k_edge<<<egrid, 256>>>(ea, W1, W2, b2);                          // 4  <- profiled slot
    k_out<<<(NB * NNODES * 32 + 255) / 256, 256>>>(W3, b3, out);     // 5
}

// round 16
// speedup vs baseline: 2.4049x; 1.0645x over previous
#include <cuda_runtime.h>
#include <cuda_bf16.h>

#define NNODES 50000
#define NEDGES 800000
#define NB 4
#define NIN 32
#define H2 30

typedef unsigned long long ull;

#define CONV_BLOCKS (NEDGES / 256)                       // 3125
#define PRE_BLOCKS  ((NB * NNODES * 32) / 256)           // 25000
#define ROWB 80                                          // staging row stride (bytes)
#define HROWB 144                                        // h-bounce row stride (bytes)

// ---------------- device scratch ----------------
__device__ double g_stats[2];
__device__ float  g_norm[2];
__device__ int    g_is64;
__device__ int    g_src[NEDGES];
__device__ int    g_tgt[NEDGES];
__device__ __align__(16) __nv_bfloat16 g_Pb[NB * NNODES * 32];
__device__ __align__(16) __nv_bfloat16 g_Qb[NB * NNODES * 32];
__device__ __align__(16) float g_acc[NB * NNODES * 32];

__device__ __forceinline__ float sigm(float x) {
    return __fdividef(1.0f, 1.0f + __expf(-x));
}
__device__ __forceinline__ float sigm_fast(float x) {
    float t;
    asm("tanh.approx.f32 %0, %1;" : "=f"(t) : "f"(x * 0.5f));
    return fmaf(0.5f, t, 0.5f);
}
__device__ __forceinline__ ull pack2(float lo, float hi) {
    ull r;
    asm("mov.b64 %0, {%1,%2};" : "=l"(r) : "r"(__float_as_uint(lo)), "r"(__float_as_uint(hi)));
    return r;
}
__device__ __forceinline__ ull bcast2(float v) {
    ull r;
    asm("mov.b64 %0, {%1,%1};" : "=l"(r) : "r"(__float_as_uint(v)));
    return r;
}

// ---------------- 1. detect dtype + zero stats ----------------
__global__ void k_detect(const int* __restrict__ ei) {
    int odd_or = 0;
    for (int k = 1; k < 128; k += 2) odd_or |= ei[k];
    g_is64 = (odd_or == 0) ? 1 : 0;
    g_stats[0] = 0.0;
    g_stats[1] = 0.0;
}

// ---------------- 2. megakernel: convert+stats | precompute+zero ----------------
__global__ void k_prep(const int* __restrict__ ei, const float* __restrict__ ea,
                       const float* __restrict__ x, const float* __restrict__ W1,
                       const float* __restrict__ b1) {
    if (blockIdx.x < CONV_BLOCKS) {
        __shared__ float s1[8], s2[8];
        int e = blockIdx.x * 256 + threadIdx.x;          // grid covers exactly NEDGES
        int s, t;
        if (g_is64) {
            const long long* e64 = (const long long*)ei;
            s = (int)e64[e];
            t = (int)e64[NEDGES + e];
        } else {
            s = ei[e];
            t = ei[NEDGES + e];
        }
        s = min(max(s, 0), NNODES - 1);
        t = min(max(t, 0), NNODES - 1);
        g_src[e] = s;
        g_tgt[e] = t;

        float v = ea[e];
        float v1 = v, v2 = v * v;
        #pragma unroll
        for (int o = 16; o > 0; o >>= 1) {
            v1 += __shfl_xor_sync(0xffffffffu, v1, o);
            v2 += __shfl_xor_sync(0xffffffffu, v2, o);
        }
        int w = threadIdx.x >> 5;
        if ((threadIdx.x & 31) == 0) { s1[w] = v1; s2[w] = v2; }
        __syncthreads();
        if (threadIdx.x == 0) {
            float t1 = 0.0f, t2 = 0.0f;
            #pragma unroll
            for (int i = 0; i < 8; i++) { t1 += s1[i]; t2 += s2[i]; }
            atomicAdd(&g_stats[0], (double)t1);
            atomicAdd(&g_stats[1], (double)t2);
        }
    } else {
        int tid = (blockIdx.x - CONV_BLOCKS) * 256 + threadIdx.x;
        int j   = tid & 31;
        int row = tid >> 5;
        const float* xr = x + (size_t)row * NIN;
        float p = 0.0f;
        float q = b1[j];
        #pragma unroll
        for (int i = 0; i < NIN; i++) {
            float xi = __ldg(&xr[i]);
            p = fmaf(xi, __ldg(&W1[i * 32 + j]), p);
            q = fmaf(xi, __ldg(&W1[(32 + i) * 32 + j]), q);
        }
        g_Pb[tid] = __float2bfloat16(p);
        g_Qb[tid] = __float2bfloat16(q);
        g_acc[tid] = 0.0f;
    }
}

// ---------------- 3. finalize stats ----------------
__global__ void k_finalize_stats() {
    double s = g_stats[0], ss = g_stats[1];
    double n = (double)NEDGES;
    double mean = s / n;
    double var = (ss - s * s / n) / (n - 1.0);   // ddof=1
    g_norm[0] = (float)mean;
    g_norm[1] = (float)(1.0 / sqrt(var));
}

// ---------------- 4. edge kernel (PROFILED SLOT) ----------------
// Compute: 1 edge/thread. Scatter: octet-cooperative via smem bounce.
// 3 blocks/SM forced: 24 warps/SM for latency hiding.
__global__ __launch_bounds__(256, 3) void k_edge(const float* __restrict__ ea,
                                                 const float* __restrict__ W1,
                                                 const float* __restrict__ W2,
                                                 const float* __restrict__ b2) {
    __shared__ __align__(16) ull  sW2p[32 * 16];
    __shared__ float sw1c[32];
    __shared__ ull   sb2p[16];
    __shared__ __align__(16) char sBuf[256 * 2 * ROWB];  // stage P/Q; then h-bounce (256*144 fits)
    __shared__ int  sIdx[256 * 2];                       // [row]: src, tgt

    char* sP = sBuf;
    char* sQ = sBuf + 256 * ROWB;

    for (int idx = threadIdx.x; idx < 512; idx += 256) {
        int j = idx >> 4, m = idx & 15;
        float w0 = (2 * m     < H2) ? W2[j * H2 + 2 * m]     : 0.0f;
        float w1 = (2 * m + 1 < H2) ? W2[j * H2 + 2 * m + 1] : 0.0f;
        sW2p[idx] = pack2(w0, w1);
    }
    if (threadIdx.x < 32) {
        sw1c[threadIdx.x] = W1[64 * 32 + threadIdx.x];
    }
    if (threadIdx.x < 16) {
        int m = threadIdx.x;
        float d0 = (2 * m     < H2) ? b2[2 * m]     : 0.0f;
        float d1 = (2 * m + 1 < H2) ? b2[2 * m + 1] : 0.0f;
        sb2p[m] = pack2(d0, d1);
    }

    int b = blockIdx.y;
    size_t bbase = (size_t)b * NNODES;
    int e0 = blockIdx.x * 256;                    // NEDGES % 256 == 0

    // ---- cooperative gather: quad (4 lanes) loads one 64B row ----
    {
        int chunk = threadIdx.x & 3;
        int row4  = threadIdx.x >> 2;             // 0..63
        #pragma unroll
        for (int it = 0; it < 4; it++) {
            int row = row4 + it * 64;
            int e = e0 + row;
            int src = g_src[e];
            int tgt = g_tgt[e];
            const uint4* Pr = (const uint4*)(g_Pb + (bbase + src) * 32);
            const uint4* Qr = (const uint4*)(g_Qb + (bbase + tgt) * 32);
            *(uint4*)(sP + row * ROWB + chunk * 16) = Pr[chunk];
            *(uint4*)(sQ + row * ROWB + chunk * 16) = Qr[chunk];
            if (chunk == 0) {
                sIdx[row * 2 + 0] = src;
                sIdx[row * 2 + 1] = tgt;
            }
        }
    }
    __syncthreads();

    int e = e0 + threadIdx.x;
    float ean = (ea[e] - g_norm[0]) * g_norm[1];

    const uint4* myP = (const uint4*)(sP + threadIdx.x * ROWB);
    const uint4* myQ = (const uint4*)(sQ + threadIdx.x * ROWB);
    uint4 pv[4], qv[4];
    #pragma unroll
    for (int m = 0; m < 4; m++) { pv[m] = myP[m]; qv[m] = myQ[m]; }

    const __nv_bfloat162* pb = (const __nv_bfloat162*)pv;
    const __nv_bfloat162* qb = (const __nv_bfloat162*)qv;

    float z1[32];
    #pragma unroll
    for (int m = 0; m < 16; m++) {
        float2 pf = __bfloat1622float2(pb[m]);
        float2 qf = __bfloat1622float2(qb[m]);
        z1[2 * m + 0] = pf.x + qf.x + ean * sw1c[2 * m + 0];
        z1[2 * m + 1] = pf.y + qf.y + ean * sw1c[2 * m + 1];
    }

    ull h2p[16];
    #pragma unroll
    for (int m = 0; m < 16; m++) h2p[m] = sb2p[m];

    #pragma unroll
    for (int j = 0; j < 32; j++) {
        ull ap = bcast2(sigm_fast(z1[j]));
        const ulonglong2* wr = (const ulonglong2*)&sW2p[j * 16];
        #pragma unroll
        for (int m = 0; m < 8; m++) {
            ulonglong2 w = wr[m];
            asm("fma.rn.f32x2 %0, %1, %2, %0;" : "+l"(h2p[2 * m + 0]) : "l"(ap), "l"(w.x));
            asm("fma.rn.f32x2 %0, %1, %2, %0;" : "+l"(h2p[2 * m + 1]) : "l"(ap), "l"(w.y));
        }
    }

    float h2[32];
    #pragma unroll
    for (int m = 0; m < 16; m++) {
        unsigned lo, hi;
        asm("mov.b64 {%0,%1}, %2;" : "=r"(lo), "=r"(hi) : "l"(h2p[m]));
        h2[2 * m + 0] = sigm_fast(__uint_as_float(lo));
        h2[2 * m + 1] = sigm_fast(__uint_as_float(hi));
    }
    h2[30] = 0.0f;   // pad channels must not scatter sigmoid(0)
    h2[31] = 0.0f;

    // ---- bounce h2 through smem (overwrites staging buffer) ----
    __syncthreads();                              // all P/Q reads done
    {
        float4* myH = (float4*)(sBuf + threadIdx.x * HROWB);
        #pragma unroll
        for (int m = 0; m < 8; m++)
            myH[m] = make_float4(h2[4 * m + 0], h2[4 * m + 1], h2[4 * m + 2], h2[4 * m + 3]);
    }
    __syncthreads();

    // ---- octet-cooperative scatter: 8 lanes = 1 edge, lane owns chunk oc ----
    {
        int oc  = threadIdx.x & 7;                // 16B chunk 0..7
        int oct = threadIdx.x >> 3;               // 0..31
        #pragma unroll
        for (int it = 0; it < 8; it++) {
            int row = oct + it * 32;              // 0..255
            int src = sIdx[row * 2 + 0];
            int tgt = sIdx[row * 2 + 1];
            float4 hv = *(const float4*)(sBuf + row * HROWB + oc * 16);
            atomicAdd((float4*)&g_acc[(bbase + tgt) * 32 + oc * 4], hv);
            atomicAdd((float4*)&g_acc[(bbase + src) * 32 + oc * 4],
                      make_float4(-hv.x, -hv.y, -hv.z, -hv.w));
        }
    }
}

// ---------------- 5. epilogue ----------------
__global__ void k_out(const float* __restrict__ W3,
                      const float* __restrict__ b3,
                      float* __restrict__ out) {
    int tid = blockIdx.x * 256 + threadIdx.x;
    if (tid >= NB * NNODES * 32) return;
    int j   = tid & 31;
    int row = tid >> 5;
    const float* ar = &g_acc[(size_t)row * 32];
    float o = b3[j];
    #pragma unroll
    for (int k = 0; k < H2; k++) {
        o = fmaf(ar[k], __ldg(&W3[k * 32 + j]), o);
    }
    out[tid] = sigm(o);
}

// ---------------- launch ----------------
extern "C" void kernel_launch(void* const* d_in, const int* in_sizes, int n_in,
                              void* d_out, int out_size) {
    const void* p_x = 0;  const void* p_ei = 0; const void* p_ea = 0;
    const void* p_W1 = 0; const void* p_b1 = 0; const void* p_W2 = 0;
    const void* p_b2 = 0; const void* p_W3 = 0; const void* p_b3 = 0;
    for (int i = 0; i < n_in; i++) {
        int s = in_sizes[i];
        const void* p = d_in[i];
        if      (s == NB * NNODES * NIN)  p_x = p;
        else if (s == 2 * NEDGES)         p_ei = p;
        else if (s == NEDGES)             p_ea = p;
        else if (s == (2 * NIN + 1) * 32) p_W1 = p;
        else if (s == 32 * H2)            { if (!p_W2) p_W2 = p; else p_W3 = p; }
        else if (s == 32)                 { if (!p_b1) p_b1 = p; else p_b3 = p; }
        else if (s == H2)                 p_b2 = p;
    }
    const float* x  = (const float*)p_x;
    const int*   ei = (const int*)p_ei;
    const float* ea = (const float*)p_ea;
    const float* W1 = (const float*)p_W1;
    const float* b1 = (const float*)p_b1;
    const float* W2 = (const float*)p_W2;
    const float* b2 = (const float*)p_b2;
    const float* W3 = (const float*)p_W3;
    const float* b3 = (const float*)p_b3;
    float* out = (float*)d_out;

    k_detect<<<1, 1>>>(ei);                                          // 1
    k_prep<<<CONV_BLOCKS + PRE_BLOCKS, 256>>>(ei, ea, x, W1, b1);    // 2
    k_finalize_stats<<<1, 1>>>();                                    // 3
    dim3 egrid(CONV_BLOCKS, NB);
    k_edge<<<egrid, 256>>>(ea, W1, W2, b2);                          // 4  <- profiled slot
    k_out<<<(NB * NNODES * 32 + 255) / 256, 256>>>(W3, b3, out);     // 5
}

// round 17
// speedup vs baseline: 2.4854x; 1.0335x over previous
#include <cuda_runtime.h>
#include <cuda_bf16.h>

#define NNODES 50000
#define NEDGES 800000
#define NB 4
#define NIN 32
#define H2 30

typedef unsigned long long ull;

#define CONV_BLOCKS (NEDGES / 256)                       // 3125
#define PRE_BLOCKS  ((NB * NNODES * 32) / 256)           // 25000
#define ROWB 80                                          // staging row stride (bytes)
#define HROWB 144                                        // h-bounce row stride (bytes)

// ---------------- device scratch ----------------
__device__ double g_stats[2];
__device__ float  g_norm[2];
__device__ int    g_is64;
__device__ int    g_src[NEDGES];
__device__ int    g_tgt[NEDGES];
__device__ __align__(16) __nv_bfloat16 g_Pb[NB * NNODES * 32];
__device__ __align__(16) __nv_bfloat16 g_Qb[NB * NNODES * 32];
__device__ __align__(16) float g_acc[NB * NNODES * 32];

__device__ __forceinline__ float sigm(float x) {
    return __fdividef(1.0f, 1.0f + __expf(-x));
}
__device__ __forceinline__ float sigm_fast(float x) {
    float t;
    asm("tanh.approx.f32 %0, %1;" : "=f"(t) : "f"(x * 0.5f));
    return fmaf(0.5f, t, 0.5f);
}
__device__ __forceinline__ ull pack2(float lo, float hi) {
    ull r;
    asm("mov.b64 %0, {%1,%2};" : "=l"(r) : "r"(__float_as_uint(lo)), "r"(__float_as_uint(hi)));
    return r;
}
__device__ __forceinline__ ull bcast2(float v) {
    ull r;
    asm("mov.b64 %0, {%1,%1};" : "=l"(r) : "r"(__float_as_uint(v)));
    return r;
}

// ---------------- 1. detect dtype + zero stats ----------------
__global__ void k_detect(const int* __restrict__ ei) {
    int odd_or = 0;
    for (int k = 1; k < 128; k += 2) odd_or |= ei[k];
    g_is64 = (odd_or == 0) ? 1 : 0;
    g_stats[0] = 0.0;
    g_stats[1] = 0.0;
}

// ---------------- 2. megakernel: convert+stats | precompute+zero ----------------
__global__ void k_prep(const int* __restrict__ ei, const float* __restrict__ ea,
                       const float* __restrict__ x, const float* __restrict__ W1,
                       const float* __restrict__ b1) {
    if (blockIdx.x < CONV_BLOCKS) {
        __shared__ float s1[8], s2[8];
        int e = blockIdx.x * 256 + threadIdx.x;          // grid covers exactly NEDGES
        int s, t;
        if (g_is64) {
            const long long* e64 = (const long long*)ei;
            s = (int)e64[e];
            t = (int)e64[NEDGES + e];
        } else {
            s = ei[e];
            t = ei[NEDGES + e];
        }
        s = min(max(s, 0), NNODES - 1);
        t = min(max(t, 0), NNODES - 1);
        g_src[e] = s;
        g_tgt[e] = t;

        float v = ea[e];
        float v1 = v, v2 = v * v;
        #pragma unroll
        for (int o = 16; o > 0; o >>= 1) {
            v1 += __shfl_xor_sync(0xffffffffu, v1, o);
            v2 += __shfl_xor_sync(0xffffffffu, v2, o);
        }
        int w = threadIdx.x >> 5;
        if ((threadIdx.x & 31) == 0) { s1[w] = v1; s2[w] = v2; }
        __syncthreads();
        if (threadIdx.x == 0) {
            float t1 = 0.0f, t2 = 0.0f;
            #pragma unroll
            for (int i = 0; i < 8; i++) { t1 += s1[i]; t2 += s2[i]; }
            atomicAdd(&g_stats[0], (double)t1);
            atomicAdd(&g_stats[1], (double)t2);
        }
    } else {
        int tid = (blockIdx.x - CONV_BLOCKS) * 256 + threadIdx.x;
        int j   = tid & 31;
        int row = tid >> 5;
        const float* xr = x + (size_t)row * NIN;
        float p = 0.0f;
        float q = b1[j];
        #pragma unroll
        for (int i = 0; i < NIN; i++) {
            float xi = __ldg(&xr[i]);
            p = fmaf(xi, __ldg(&W1[i * 32 + j]), p);
            q = fmaf(xi, __ldg(&W1[(32 + i) * 32 + j]), q);
        }
        g_Pb[tid] = __float2bfloat16(p);
        g_Qb[tid] = __float2bfloat16(q);
        g_acc[tid] = 0.0f;
    }
}

// ---------------- 3. finalize stats ----------------
__global__ void k_finalize_stats() {
    double s = g_stats[0], ss = g_stats[1];
    double n = (double)NEDGES;
    double mean = s / n;
    double var = (ss - s * s / n) / (n - 1.0);   // ddof=1
    g_norm[0] = (float)mean;
    g_norm[1] = (float)(1.0 / sqrt(var));
}

// ---------------- 4. edge kernel (PROFILED SLOT) ----------------
// Compute: 1 edge/thread layer-1. Layer-2: lane pairs split channels
// (even lane: ch[0,16), odd: ch[16,32)) for both edges of the pair —
// halves the W2 shared-load stream. Scatter: octet-cooperative bounce.
__global__ __launch_bounds__(256, 3) void k_edge(const float* __restrict__ ea,
                                                 const float* __restrict__ W1,
                                                 const float* __restrict__ W2,
                                                 const float* __restrict__ b2) {
    __shared__ __align__(16) ull  sW2p[32 * 16];
    __shared__ float sw1c[32];
    __shared__ ull   sb2p[16];
    __shared__ __align__(16) char sBuf[256 * 2 * ROWB];  // stage P/Q; then h-bounce (256*144 fits)
    __shared__ int  sIdx[256 * 2];                       // [row]: src, tgt

    char* sP = sBuf;
    char* sQ = sBuf + 256 * ROWB;

    for (int idx = threadIdx.x; idx < 512; idx += 256) {
        int j = idx >> 4, m = idx & 15;
        float w0 = (2 * m     < H2) ? W2[j * H2 + 2 * m]     : 0.0f;
        float w1 = (2 * m + 1 < H2) ? W2[j * H2 + 2 * m + 1] : 0.0f;
        sW2p[idx] = pack2(w0, w1);
    }
    if (threadIdx.x < 32) {
        sw1c[threadIdx.x] = W1[64 * 32 + threadIdx.x];
    }
    if (threadIdx.x < 16) {
        int m = threadIdx.x;
        float d0 = (2 * m     < H2) ? b2[2 * m]     : 0.0f;
        float d1 = (2 * m + 1 < H2) ? b2[2 * m + 1] : 0.0f;
        sb2p[m] = pack2(d0, d1);
    }

    int b = blockIdx.y;
    size_t bbase = (size_t)b * NNODES;
    int e0 = blockIdx.x * 256;                    // NEDGES % 256 == 0

    // ---- cooperative gather: quad (4 lanes) loads one 64B row ----
    {
        int chunk = threadIdx.x & 3;
        int row4  = threadIdx.x >> 2;             // 0..63
        #pragma unroll
        for (int it = 0; it < 4; it++) {
            int row = row4 + it * 64;
            int e = e0 + row;
            int src = g_src[e];
            int tgt = g_tgt[e];
            const uint4* Pr = (const uint4*)(g_Pb + (bbase + src) * 32);
            const uint4* Qr = (const uint4*)(g_Qb + (bbase + tgt) * 32);
            *(uint4*)(sP + row * ROWB + chunk * 16) = Pr[chunk];
            *(uint4*)(sQ + row * ROWB + chunk * 16) = Qr[chunk];
            if (chunk == 0) {
                sIdx[row * 2 + 0] = src;
                sIdx[row * 2 + 1] = tgt;
            }
        }
    }
    __syncthreads();

    int e = e0 + threadIdx.x;
    float ean = (ea[e] - g_norm[0]) * g_norm[1];

    const uint4* myP = (const uint4*)(sP + threadIdx.x * ROWB);
    const uint4* myQ = (const uint4*)(sQ + threadIdx.x * ROWB);
    uint4 pv[4], qv[4];
    #pragma unroll
    for (int m = 0; m < 4; m++) { pv[m] = myP[m]; qv[m] = myQ[m]; }

    const __nv_bfloat162* pb = (const __nv_bfloat162*)pv;
    const __nv_bfloat162* qb = (const __nv_bfloat162*)qv;

    float z1[32];
    #pragma unroll
    for (int m = 0; m < 16; m++) {
        float2 pf = __bfloat1622float2(pb[m]);
        float2 qf = __bfloat1622float2(qb[m]);
        z1[2 * m + 0] = pf.x + qf.x + ean * sw1c[2 * m + 0];
        z1[2 * m + 1] = pf.y + qf.y + ean * sw1c[2 * m + 1];
    }

    // ---- layer-2: lane-pair channel split ----
    int half = threadIdx.x & 1;                   // 0: ch[0,16), 1: ch[16,32)

    ull h0[8], h1[8];                             // edge (t&~1), edge (t|1): 16 ch each
    #pragma unroll
    for (int i = 0; i < 8; i++) { h0[i] = sb2p[half * 8 + i]; h1[i] = h0[i]; }

    #pragma unroll
    for (int j = 0; j < 32; j++) {
        float aj  = sigm_fast(z1[j]);             // own edge's activation
        float ajp = __shfl_xor_sync(0xffffffffu, aj, 1);   // partner edge's
        float aE0 = half ? ajp : aj;              // edge (t & ~1)
        float aE1 = half ? aj : ajp;              // edge (t | 1)
        ull ap0 = bcast2(aE0);
        ull ap1 = bcast2(aE1);
        const ulonglong2* wr = (const ulonglong2*)&sW2p[j * 16 + half * 8];
        ulonglong2 wa = wr[0];                    // ch 0..3 of this half
        ulonglong2 wb = wr[1];                    // ch 4..7
        ulonglong2 wc = wr[2];                    // ch 8..11
        ulonglong2 wd = wr[3];                    // ch 12..15
        asm("fma.rn.f32x2 %0, %1, %2, %0;" : "+l"(h0[0]) : "l"(ap0), "l"(wa.x));
        asm("fma.rn.f32x2 %0, %1, %2, %0;" : "+l"(h0[1]) : "l"(ap0), "l"(wa.y));
        asm("fma.rn.f32x2 %0, %1, %2, %0;" : "+l"(h0[2]) : "l"(ap0), "l"(wb.x));
        asm("fma.rn.f32x2 %0, %1, %2, %0;" : "+l"(h0[3]) : "l"(ap0), "l"(wb.y));
        asm("fma.rn.f32x2 %0, %1, %2, %0;" : "+l"(h0[4]) : "l"(ap0), "l"(wc.x));
        asm("fma.rn.f32x2 %0, %1, %2, %0;" : "+l"(h0[5]) : "l"(ap0), "l"(wc.y));
        asm("fma.rn.f32x2 %0, %1, %2, %0;" : "+l"(h0[6]) : "l"(ap0), "l"(wd.x));
        asm("fma.rn.f32x2 %0, %1, %2, %0;" : "+l"(h0[7]) : "l"(ap0), "l"(wd.y));
        asm("fma.rn.f32x2 %0, %1, %2, %0;" : "+l"(h1[0]) : "l"(ap1), "l"(wa.x));
        asm("fma.rn.f32x2 %0, %1, %2, %0;" : "+l"(h1[1]) : "l"(ap1), "l"(wa.y));
        asm("fma.rn.f32x2 %0, %1, %2, %0;" : "+l"(h1[2]) : "l"(ap1), "l"(wb.x));
        asm("fma.rn.f32x2 %0, %1, %2, %0;" : "+l"(h1[3]) : "l"(ap1), "l"(wb.y));
        asm("fma.rn.f32x2 %0, %1, %2, %0;" : "+l"(h1[4]) : "l"(ap1), "l"(wc.x));
        asm("fma.rn.f32x2 %0, %1, %2, %0;" : "+l"(h1[5]) : "l"(ap1), "l"(wc.y));
        asm("fma.rn.f32x2 %0, %1, %2, %0;" : "+l"(h1[6]) : "l"(ap1), "l"(wd.x));
        asm("fma.rn.f32x2 %0, %1, %2, %0;" : "+l"(h1[7]) : "l"(ap1), "l"(wd.y));
    }

    // sigmoid on the 16 channels of each pair edge
    float h2a[16], h2b[16];
    #pragma unroll
    for (int i = 0; i < 8; i++) {
        unsigned lo, hi;
        asm("mov.b64 {%0,%1}, %2;" : "=r"(lo), "=r"(hi) : "l"(h0[i]));
        h2a[2 * i + 0] = sigm_fast(__uint_as_float(lo));
        h2a[2 * i + 1] = sigm_fast(__uint_as_float(hi));
        asm("mov.b64 {%0,%1}, %2;" : "=r"(lo), "=r"(hi) : "l"(h1[i]));
        h2b[2 * i + 0] = sigm_fast(__uint_as_float(lo));
        h2b[2 * i + 1] = sigm_fast(__uint_as_float(hi));
    }
    if (half) {                                    // channels 30,31 are pads
        h2a[14] = 0.0f; h2a[15] = 0.0f;
        h2b[14] = 0.0f; h2b[15] = 0.0f;
    }

    // ---- bounce h through smem (overwrites staging buffer) ----
    __syncthreads();                              // all P/Q reads done
    {
        int r0 = threadIdx.x & ~1;                // pair edge rows
        int r1 = threadIdx.x | 1;
        float4* wA = (float4*)(sBuf + r0 * HROWB + half * 64);
        float4* wB = (float4*)(sBuf + r1 * HROWB + half * 64);
        #pragma unroll
        for (int i = 0; i < 4; i++) {
            wA[i] = make_float4(h2a[4 * i + 0], h2a[4 * i + 1], h2a[4 * i + 2], h2a[4 * i + 3]);
            wB[i] = make_float4(h2b[4 * i + 0], h2b[4 * i + 1], h2b[4 * i + 2], h2b[4 * i + 3]);
        }
    }
    __syncthreads();

    // ---- octet-cooperative scatter: 8 lanes = 1 edge, lane owns chunk oc ----
    {
        int oc  = threadIdx.x & 7;                // 16B chunk 0..7
        int oct = threadIdx.x >> 3;               // 0..31
        #pragma unroll
        for (int it = 0; it < 8; it++) {
            int row = oct + it * 32;              // 0..255
            int src = sIdx[row * 2 + 0];
            int tgt = sIdx[row * 2 + 1];
            float4 hv = *(const float4*)(sBuf + row * HROWB + oc * 16);
            atomicAdd((float4*)&g_acc[(bbase + tgt) * 32 + oc * 4], hv);
            atomicAdd((float4*)&g_acc[(bbase + src) * 32 + oc * 4],
                      make_float4(-hv.x, -hv.y, -hv.z, -hv.w));
        }
    }
}

// ---------------- 5. epilogue ----------------
__global__ void k_out(const float* __restrict__ W3,
                      const float* __restrict__ b3,
                      float* __restrict__ out) {
    int tid = blockIdx.x * 256 + threadIdx.x;
    if (tid >= NB * NNODES * 32) return;
    int j   = tid & 31;
    int row = tid >> 5;
    const float* ar = &g_acc[(size_t)row * 32];
    float o = b3[j];
    #pragma unroll
    for (int k = 0; k < H2; k++) {
        o = fmaf(ar[k], __ldg(&W3[k * 32 + j]), o);
    }
    out[tid] = sigm(o);
}

// ---------------- launch ----------------
extern "C" void kernel_launch(void* const* d_in, const int* in_sizes, int n_in,
                              void* d_out, int out_size) {
    const void* p_x = 0;  const void* p_ei = 0; const void* p_ea = 0;
    const void* p_W1 = 0; const void* p_b1 = 0; const void* p_W2 = 0;
    const void* p_b2 = 0; const void* p_W3 = 0; const void* p_b3 = 0;
    for (int i = 0; i < n_in; i++) {
        int s = in_sizes[i];
        const void* p = d_in[i];
        if      (s == NB * NNODES * NIN)  p_x = p;
        else if (s == 2 * NEDGES)         p_ei = p;
        else if (s == NEDGES)             p_ea = p;
        else if (s == (2 * NIN + 1) * 32) p_W1 = p;
        else if (s == 32 * H2)            { if (!p_W2) p_W2 = p; else p_W3 = p; }
        else if (s == 32)                 { if (!p_b1) p_b1 = p; else p_b3 = p; }
        else if (s == H2)                 p_b2 = p;
    }
    const float* x  = (const float*)p_x;
    const int*   ei = (const int*)p_ei;
    const float* ea = (const float*)p_ea;
    const float* W1 = (const float*)p_W1;
    const float* b1 = (const float*)p_b1;
    const float* W2 = (const float*)p_W2;
    const float* b2 = (const float*)p_b2;
    const float* W3 = (const float*)p_W3;
    const float* b3 = (const float*)p_b3;
    float* out = (float*)d_out;

    k_detect<<<1, 1>>>(ei);                                          // 1
    k_prep<<<CONV_BLOCKS + PRE_BLOCKS, 256>>>(ei, ea, x, W1, b1);    // 2
    k_finalize_stats<<<1, 1>>>();                                    // 3
    dim3 egrid(CONV_BLOCKS, NB);
    k_edge<<<egrid, 256>>>(ea, W1, W2, b2);                          // 4  <- profiled slot
    k_out<<<(NB * NNODES * 32 + 255) / 256, 256>>>(W3, b3, out);     // 5
}